// round 14
// baseline (speedup 1.0000x reference)
#include <cuda_runtime.h>

// GRU: B=4096, T=512, I=32, H=64. out = final hidden (B, H) fp32.
// Two-group software pipeline: CTA's 32 rows split into G0 (0-15), G1 (16-31)
// (independent recurrences). Per step t:
//   Phase A: epilogue(G1, t-1) overlapped with GEMM(G0, t)   [bar]
//   Phase B: epilogue(G0, t)   overlapped with GEMM(G1, t)   [bar]
// Per SMSP s: warps {s, 4+s, 8+s} = h0 (k 0..31), h1 (k 32..63), xw (x-proj,
// self-contained XD staging). 4-row GEMM tiles -> 12 accumulators/warp (~100
// regs, deep load pipelining). All exchange smsp-local; per-smsp named bars.
// Math: packed fma.rn.f32x2 on duplicated smem operands.

#define THREADS      384
#define ROWS_PER_CTA 32
#define I_DIM        32
#define H_DIM        64
#define G_DIM        192
#define S_DUP        68
#define S_XD         36

#define WS_FLOATS    (96 * G_DIM)      // 18432
#define HD_FLOATS    (H_DIM * S_DUP)   // 4352
#define XD_FLOATS    (I_DIM * S_XD)    // 1152 per buffer; 4 buffers (g, parity)
#define SCH_U64      (2 * 4 * 3 * 4 * 32)   // g, row, acc, smsp, lane = 3072
#define SCX_U64      (2 * 4 * 3 * 4 * 32)
#define SMEM_BYTES   ((WS_FLOATS + HD_FLOATS + 4 * XD_FLOATS) * 4 + (SCH_U64 + SCX_U64) * 8)

typedef unsigned long long u64;

__device__ __forceinline__ void fma2(u64& d, u64 a, u64 b) {
    asm("fma.rn.f32x2 %0, %1, %2, %0;" : "+l"(d) : "l"(a), "l"(b));
}
__device__ __forceinline__ u64 add2(u64 a, u64 b) {
    u64 r;
    asm("add.rn.f32x2 %0, %1, %2;" : "=l"(r) : "l"(a), "l"(b));
    return r;
}
__device__ __forceinline__ float2 upk(u64 v) {
    float2 f;
    asm("mov.b64 {%0, %1}, %2;" : "=f"(f.x), "=f"(f.y) : "l"(v));
    return f;
}
__device__ __forceinline__ float tanh_hw(float x) {
    float y;
    asm("tanh.approx.f32 %0, %1;" : "=f"(y) : "f"(x));
    return y;
}
__device__ __forceinline__ float sig_hw(float x) {
    return fmaf(tanh_hw(0.5f * x), 0.5f, 0.5f);
}
__device__ __forceinline__ float tanh_acc(float x) {
    return __fdividef(2.0f, 1.0f + __expf(-2.0f * x)) - 1.0f;
}
__device__ __forceinline__ void barx(int id) {
    asm volatile("bar.sync %0, %1;" :: "r"(id), "r"(96) : "memory");
}

struct GateB { float bR0, bR1, bZ0, bZ1, bIN0, bIN1, bHN0, bHN1; };

__device__ __forceinline__ void gate_row(u64 sR, u64 sZ, u64 sN, u64 sX,
                                         const GateB& b, float2& h01) {
    float2 uR = upk(sR), uZ = upk(sZ), uH = upk(sN), uX = upk(sX);
    float r0g = sig_hw(uR.x + b.bR0);
    float z0g = sig_hw(uZ.x + b.bZ0);
    float n0  = tanh_acc(uX.x + b.bIN0 + r0g * (uH.x + b.bHN0));
    float r1g = sig_hw(uR.y + b.bR1);
    float z1g = sig_hw(uZ.y + b.bZ1);
    float n1  = tanh_acc(uX.y + b.bIN1 + r1g * (uH.y + b.bHN1));
    h01.x = n0 + z0g * (h01.x - n0);
    h01.y = n1 + z1g * (h01.y - n1);
}

// 4-row GEMM k-step: ab = A base (dup layout), wb = &Ws[k*G_DIM + j0]
#define KG4(ab, wb, R, Z, N)                                                 \
    {                                                                        \
        ulonglong2 A0 = *reinterpret_cast<const ulonglong2*>(ab);            \
        ulonglong2 A1 = *reinterpret_cast<const ulonglong2*>((ab) + 4);      \
        u64 wr = *reinterpret_cast<const u64*>(wb);                          \
        u64 wz = *reinterpret_cast<const u64*>((wb) + 64);                   \
        u64 wn = *reinterpret_cast<const u64*>((wb) + 128);                  \
        fma2(R[0], A0.x, wr); fma2(R[1], A0.y, wr);                          \
        fma2(R[2], A1.x, wr); fma2(R[3], A1.y, wr);                          \
        fma2(Z[0], A0.x, wz); fma2(Z[1], A0.y, wz);                          \
        fma2(Z[2], A1.x, wz); fma2(Z[3], A1.y, wz);                          \
        fma2(N[0], A0.x, wn); fma2(N[1], A0.y, wn);                          \
        fma2(N[2], A1.x, wn); fma2(N[3], A1.y, wn);                          \
    }

#define SCHI(g, l, a)  (((((g) * 4 + (l)) * 3 + (a)) * 4 + s) * 32 + c)
#define SCXI(g, l, a)  (((((g) * 4 + (l)) * 3 + (a)) * 4 + s) * 32 + c)

#define SHIPH(g, l, R, Z, N)                                                 \
    SCH[SCHI(g, l, 0)] = R[l];                                               \
    SCH[SCHI(g, l, 1)] = Z[l];                                               \
    SCH[SCHI(g, l, 2)] = N[l];

#define SHIPX(g, l, R, Z, X)                                                 \
    SCX[SCXI(g, l, 0)] = R[l];                                               \
    SCX[SCXI(g, l, 1)] = Z[l];                                               \
    SCX[SCXI(g, l, 2)] = X[l];

// epilogue for row l (literal!) of group g; GR = global CTA row; HH = h regs
#define EPIROW(g, l, R, Z, N, HH, GR)                                        \
    {                                                                        \
        u64 sR = add2(add2(R[l], SCH[SCHI(g, l, 0)]), SCX[SCXI(g, l, 0)]);   \
        u64 sZ = add2(add2(Z[l], SCH[SCHI(g, l, 1)]), SCX[SCXI(g, l, 1)]);   \
        u64 sN = add2(N[l], SCH[SCHI(g, l, 2)]);                             \
        u64 sX = SCX[SCXI(g, l, 2)];                                         \
        gate_row(sR, sZ, sN, sX, gb, HH);                                    \
        *reinterpret_cast<float2*>(&HD[j0 * S_DUP + 2 * (GR)]) =             \
            make_float2(HH.x, HH.x);                                         \
        *reinterpret_cast<float2*>(&HD[(j0 + 1) * S_DUP + 2 * (GR)]) =       \
            make_float2(HH.y, HH.y);                                         \
    }

__global__ void __launch_bounds__(THREADS, 1)
gru_fwd_kernel(const float* __restrict__ seq,
               const float* __restrict__ W_ih,
               const float* __restrict__ W_hh,
               const float* __restrict__ b_ih,
               const float* __restrict__ b_hh,
               float* __restrict__ out,
               int B, int T)
{
    extern __shared__ float sm[];
    float* Ws  = sm;
    float* HD  = sm + WS_FLOATS;
    float* XD  = HD + HD_FLOATS;                 // 4 buffers: (g*2 + parity)
    u64*   SCH = (u64*)(XD + 4 * XD_FLOATS);
    u64*   SCX = SCH + SCH_U64;

    const int tid = threadIdx.x;
    const int w   = tid >> 5;
    const int c   = tid & 31;
    const bool is_x = (w >= 8);
    const int s   = is_x ? (w - 8) : (w & 3);
    const int grp = w >> 2;                      // 0,1 = h-halves; 2 = x
    const int bb  = blockIdx.x * ROWS_PER_CTA;
    const int j0  = 2 * c;
    const int bid = 1 + s;

    // ---- one-time init ----
    for (int idx = tid; idx < G_DIM * H_DIM; idx += THREADS) {
        int gg = idx / H_DIM, k = idx % H_DIM;
        Ws[k * G_DIM + gg] = W_hh[idx];
    }
    for (int idx = tid; idx < G_DIM * I_DIM; idx += THREADS) {
        int gg = idx / I_DIM, i = idx % I_DIM;
        Ws[(H_DIM + i) * G_DIM + gg] = W_ih[idx];
    }
    for (int idx = tid; idx < HD_FLOATS; idx += THREADS) HD[idx] = 0.0f;

    GateB gb;
    gb.bR0  = b_ih[j0]      + b_hh[j0];
    gb.bR1  = b_ih[j0 + 1]  + b_hh[j0 + 1];
    gb.bZ0  = b_ih[64 + j0] + b_hh[64 + j0];
    gb.bZ1  = b_ih[65 + j0] + b_hh[65 + j0];
    gb.bIN0 = b_ih[128 + j0]; gb.bIN1 = b_ih[129 + j0];
    gb.bHN0 = b_hh[128 + j0]; gb.bHN1 = b_hh[129 + j0];

    // xw staging geometry: lane c stages row (c>>3) of its smsp's 4-row slice
    const int lr8   = c >> 3;                    // 0..3
    const int scol4 = (c & 7) * 4;
    const int xdoff = scol4 * S_XD + 2 * (4 * s + lr8);   // group-local
    const float* xp0 = seq + (size_t)(bb + 8 * s + lr8) * T * I_DIM + scol4;
    const float* xp1 = seq + (size_t)(bb + 8 * s + 4 + lr8) * T * I_DIM + scol4;

    // prologue: xw stages x(g, 0) into XD[g][0]
    if (is_x) {
        float4 v0 = *reinterpret_cast<const float4*>(xp0);
        float4 v1 = *reinterpret_cast<const float4*>(xp1);
        #pragma unroll
        for (int i = 0; i < 4; ++i) {
            float a = (&v0.x)[i], b = (&v1.x)[i];
            *reinterpret_cast<float2*>(&XD[0 * XD_FLOATS + xdoff + i * S_XD]) =
                make_float2(a, a);
            *reinterpret_cast<float2*>(&XD[2 * XD_FLOATS + xdoff + i * S_XD]) =
                make_float2(b, b);
        }
    }
    __syncthreads();

    // persistent h-warp state
    u64 R0[4], Z0[4], N0[4], R1[4], Z1[4], N1[4];
    #pragma unroll
    for (int i = 0; i < 4; ++i) {
        R0[i] = 0; Z0[i] = 0; N0[i] = 0;
        R1[i] = 0; Z1[i] = 0; N1[i] = 0;
    }
    float2 hA0 = make_float2(0.f, 0.f), hA1 = hA0, hB0 = hA0, hB1 = hA0;

    const int rbase0 = 16 * s;                   // HD float offset, G0 rows
    const int rbase1 = 16 * s + 8;               // G1 rows
    const int own0   = (grp == 0) ? 0 : 2;       // h-warp's owned local rows

    for (int t = 0; t < T; ++t) {
        const int par  = t & 1;
        const int parn = par ^ 1;

        // ================= PHASE A: epi(G1, t-1) + GEMM(G0, t) =============
        if (!is_x) {
            if (t > 0) {
                if (grp == 0) {
                    EPIROW(1, 0, R1, Z1, N1, hB0, 8 * s + 4)
                    EPIROW(1, 1, R1, Z1, N1, hB1, 8 * s + 5)
                } else {
                    EPIROW(1, 2, R1, Z1, N1, hB0, 8 * s + 6)
                    EPIROW(1, 3, R1, Z1, N1, hB1, 8 * s + 7)
                }
            }
            #pragma unroll
            for (int i = 0; i < 4; ++i) { R0[i] = 0; Z0[i] = 0; N0[i] = 0; }
            {
                const float* hb = HD + (grp * 32) * S_DUP + rbase0;
                const float* wb = Ws + (grp * 32) * G_DIM + j0;
                #pragma unroll 8
                for (int k = 0; k < 32; ++k) {
                    KG4(hb, wb, R0, Z0, N0)
                    hb += S_DUP; wb += G_DIM;
                }
            }
            if (grp == 0) { SHIPH(0, 2, R0, Z0, N0) SHIPH(0, 3, R0, Z0, N0) }
            else          { SHIPH(0, 0, R0, Z0, N0) SHIPH(0, 1, R0, Z0, N0) }
        } else {
            float4 pf;
            const bool ld = (t + 1 < T);
            if (ld) pf = *reinterpret_cast<const float4*>(xp0 + (size_t)(t + 1) * I_DIM);
            u64 R[4] = {0, 0, 0, 0}, Z[4] = {0, 0, 0, 0}, X[4] = {0, 0, 0, 0};
            {
                const float* xb = XD + par * XD_FLOATS + 8 * s;
                const float* wb = Ws + H_DIM * G_DIM + j0;
                #pragma unroll 8
                for (int k = 0; k < I_DIM; ++k) {
                    KG4(xb, wb, R, Z, X)
                    xb += S_XD; wb += G_DIM;
                }
            }
            SHIPX(0, 0, R, Z, X) SHIPX(0, 1, R, Z, X)
            SHIPX(0, 2, R, Z, X) SHIPX(0, 3, R, Z, X)
            if (ld) {
                float* dst = XD + parn * XD_FLOATS + xdoff;
                #pragma unroll
                for (int i = 0; i < 4; ++i) {
                    float v = (&pf.x)[i];
                    *reinterpret_cast<float2*>(dst + i * S_XD) = make_float2(v, v);
                }
            }
        }
        barx(bid);

        // ================= PHASE B: epi(G0, t) + GEMM(G1, t) ===============
        if (!is_x) {
            if (grp == 0) {
                EPIROW(0, 0, R0, Z0, N0, hA0, 8 * s + 0)
                EPIROW(0, 1, R0, Z0, N0, hA1, 8 * s + 1)
            } else {
                EPIROW(0, 2, R0, Z0, N0, hA0, 8 * s + 2)
                EPIROW(0, 3, R0, Z0, N0, hA1, 8 * s + 3)
            }
            #pragma unroll
            for (int i = 0; i < 4; ++i) { R1[i] = 0; Z1[i] = 0; N1[i] = 0; }
            {
                const float* hb = HD + (grp * 32) * S_DUP + rbase1;
                const float* wb = Ws + (grp * 32) * G_DIM + j0;
                #pragma unroll 8
                for (int k = 0; k < 32; ++k) {
                    KG4(hb, wb, R1, Z1, N1)
                    hb += S_DUP; wb += G_DIM;
                }
            }
            if (grp == 0) { SHIPH(1, 2, R1, Z1, N1) SHIPH(1, 3, R1, Z1, N1) }
            else          { SHIPH(1, 0, R1, Z1, N1) SHIPH(1, 1, R1, Z1, N1) }
        } else {
            float4 pf;
            const bool ld = (t + 1 < T);
            if (ld) pf = *reinterpret_cast<const float4*>(xp1 + (size_t)(t + 1) * I_DIM);
            u64 R[4] = {0, 0, 0, 0}, Z[4] = {0, 0, 0, 0}, X[4] = {0, 0, 0, 0};
            {
                const float* xb = XD + (2 + par) * XD_FLOATS + 8 * s;
                const float* wb = Ws + H_DIM * G_DIM + j0;
                #pragma unroll 8
                for (int k = 0; k < I_DIM; ++k) {
                    KG4(xb, wb, R, Z, X)
                    xb += S_XD; wb += G_DIM;
                }
            }
            SHIPX(1, 0, R, Z, X) SHIPX(1, 1, R, Z, X)
            SHIPX(1, 2, R, Z, X) SHIPX(1, 3, R, Z, X)
            if (ld) {
                float* dst = XD + (2 + parn) * XD_FLOATS + xdoff;
                #pragma unroll
                for (int i = 0; i < 4; ++i) {
                    float v = (&pf.x)[i];
                    *reinterpret_cast<float2*>(dst + i * S_XD) = make_float2(v, v);
                }
            }
        }
        barx(bid);
    }

    // ---- tail: epi(G1, T-1), then output ----
    if (!is_x) {
        if (grp == 0) {
            EPIROW(1, 0, R1, Z1, N1, hB0, 8 * s + 4)
            EPIROW(1, 1, R1, Z1, N1, hB1, 8 * s + 5)
        } else {
            EPIROW(1, 2, R1, Z1, N1, hB0, 8 * s + 6)
            EPIROW(1, 3, R1, Z1, N1, hB1, 8 * s + 7)
        }
        const int g0 = bb + 8 * s + own0;
        *reinterpret_cast<float2*>(&out[(size_t)(g0 + 0) * H_DIM + j0]) = hA0;
        *reinterpret_cast<float2*>(&out[(size_t)(g0 + 1) * H_DIM + j0]) = hA1;
        *reinterpret_cast<float2*>(&out[(size_t)(g0 + 4) * H_DIM + j0]) = hB0;
        *reinterpret_cast<float2*>(&out[(size_t)(g0 + 5) * H_DIM + j0]) = hB1;
    }
}

extern "C" void kernel_launch(void* const* d_in, const int* in_sizes, int n_in,
                              void* d_out, int out_size) {
    const float* seq  = (const float*)d_in[0];
    const float* W_ih = (const float*)d_in[1];
    const float* W_hh = (const float*)d_in[2];
    const float* b_ih = (const float*)d_in[3];
    const float* b_hh = (const float*)d_in[4];
    float* out = (float*)d_out;

    const int B = out_size / H_DIM;
    const int T = in_sizes[0] / (B * I_DIM);

    cudaFuncSetAttribute(gru_fwd_kernel,
                         cudaFuncAttributeMaxDynamicSharedMemorySize, SMEM_BYTES);

    const int grid = (B + ROWS_PER_CTA - 1) / ROWS_PER_CTA;
    gru_fwd_kernel<<<grid, THREADS, SMEM_BYTES>>>(seq, W_ih, W_hh, b_ih, b_hh,
                                                  out, B, T);
}

// round 15
// speedup vs baseline: 1.0468x; 1.0468x over previous
#include <cuda_runtime.h>

// GRU: B=4096, T=512, I=32, H=64. out = final hidden (B, H) fp32.
// 128 CTAs x 512 threads, 16 warps = 4 per SMSP group s (w&3), roles q=w>>2:
//   q0: rows 0-3, k[0,48)     q1: rows 0-3, k[48,96)
//   q2: rows 4-7, k[0,48)     q3: rows 4-7, k[48,96)
// Unified k-space [h:64 | x:32]; q-odd warps read x(t) (staged one step ahead
// by q-even warps into parity XD buffers) and keep n-gate h/x contributions in
// separate accumulators. Every warp: 576 FFMA2 in phase 1 -> balanced bar1.
// Phase 2: 2-row epilogue per warp (2-way SC reduce) + q-even stage x(t+1).
// 4-row tiles keep regs ~110 (fits the 128-reg cap at 512 thr; R7 pitfall).
// Math: packed fma.rn.f32x2 on duplicated smem operands.

#define THREADS      512
#define ROWS_PER_CTA 32
#define I_DIM        32
#define H_DIM        64
#define G_DIM        192
#define S_DUP        68

#define WS_FLOATS    (96 * G_DIM)      // 18432
#define HD_FLOATS    (H_DIM * S_DUP)   // 4352
#define XD_FLOATS    (I_DIM * S_DUP)   // 2176 (x2 parity buffers)
#define SC_U64       (2 * 4 * 4 * 4 * 32)   // pr, l, acc, smsp, lane = 4096
#define SMEM_BYTES   ((WS_FLOATS + HD_FLOATS + 2 * XD_FLOATS) * 4 + SC_U64 * 8)

typedef unsigned long long u64;

__device__ __forceinline__ void fma2(u64& d, u64 a, u64 b) {
    asm("fma.rn.f32x2 %0, %1, %2, %0;" : "+l"(d) : "l"(a), "l"(b));
}
__device__ __forceinline__ u64 add2(u64 a, u64 b) {
    u64 r;
    asm("add.rn.f32x2 %0, %1, %2;" : "=l"(r) : "l"(a), "l"(b));
    return r;
}
__device__ __forceinline__ float2 upk(u64 v) {
    float2 f;
    asm("mov.b64 {%0, %1}, %2;" : "=f"(f.x), "=f"(f.y) : "l"(v));
    return f;
}
__device__ __forceinline__ float tanh_hw(float x) {
    float y;
    asm("tanh.approx.f32 %0, %1;" : "=f"(y) : "f"(x));
    return y;
}
__device__ __forceinline__ float sig_hw(float x) {
    return fmaf(tanh_hw(0.5f * x), 0.5f, 0.5f);
}
__device__ __forceinline__ float tanh_acc(float x) {
    return __fdividef(2.0f, 1.0f + __expf(-2.0f * x)) - 1.0f;
}
__device__ __forceinline__ void barx(int id) {
    asm volatile("bar.sync %0, %1;" :: "r"(id), "r"(128) : "memory");
}

struct GateB { float bR0, bR1, bZ0, bZ1, bIN0, bIN1, bHN0, bHN1; };

__device__ __forceinline__ void gate_row(u64 sR, u64 sZ, u64 sN, u64 sX,
                                         const GateB& b, float2& h01) {
    float2 uR = upk(sR), uZ = upk(sZ), uH = upk(sN), uX = upk(sX);
    float r0g = sig_hw(uR.x + b.bR0);
    float z0g = sig_hw(uZ.x + b.bZ0);
    float n0  = tanh_acc(uX.x + b.bIN0 + r0g * (uH.x + b.bHN0));
    float r1g = sig_hw(uR.y + b.bR1);
    float z1g = sig_hw(uZ.y + b.bZ1);
    float n1  = tanh_acc(uX.y + b.bIN1 + r1g * (uH.y + b.bHN1));
    h01.x = n0 + z0g * (h01.x - n0);
    h01.y = n1 + z1g * (h01.y - n1);
}

// 4-row GEMM k-step: ab = A base (dup layout, row folded), wb = &Ws[k*G_DIM+j0]
#define KG4(ab, wb, R, Z, N)                                                 \
    {                                                                        \
        ulonglong2 A0 = *reinterpret_cast<const ulonglong2*>(ab);            \
        ulonglong2 A1 = *reinterpret_cast<const ulonglong2*>((ab) + 4);      \
        u64 wr = *reinterpret_cast<const u64*>(wb);                          \
        u64 wz = *reinterpret_cast<const u64*>((wb) + 64);                   \
        u64 wn = *reinterpret_cast<const u64*>((wb) + 128);                  \
        fma2(R[0], A0.x, wr); fma2(R[1], A0.y, wr);                          \
        fma2(R[2], A1.x, wr); fma2(R[3], A1.y, wr);                          \
        fma2(Z[0], A0.x, wz); fma2(Z[1], A0.y, wz);                          \
        fma2(Z[2], A1.x, wz); fma2(Z[3], A1.y, wz);                          \
        fma2(N[0], A0.x, wn); fma2(N[1], A0.y, wn);                          \
        fma2(N[2], A1.x, wn); fma2(N[3], A1.y, wn);                          \
    }

// SC slot: pr (row-half), l (0..3 local row), a (0..3 acc)
#define SCI(pr, l, a)  (((((pr) * 4 + (l)) * 4 + (a)) * 4 + s) * 32 + c)

__global__ void __launch_bounds__(THREADS, 1)
gru_fwd_kernel(const float* __restrict__ seq,
               const float* __restrict__ W_ih,
               const float* __restrict__ W_hh,
               const float* __restrict__ b_ih,
               const float* __restrict__ b_hh,
               float* __restrict__ out,
               int B, int T)
{
    extern __shared__ float sm[];
    float* Ws  = sm;
    float* HD  = sm + WS_FLOATS;
    float* XD  = HD + HD_FLOATS;                 // 2 parity buffers
    u64*   SCb = (u64*)(XD + 2 * XD_FLOATS);

    const int tid = threadIdx.x;
    const int w   = tid >> 5;
    const int c   = tid & 31;
    const int s   = w & 3;                       // SMSP group
    const int q   = w >> 2;                      // role 0..3
    const int pr  = q >> 1;                      // row-half 0/1
    const bool kodd = (q & 1);                   // k[48,96) warp
    const int bb  = blockIdx.x * ROWS_PER_CTA;
    const int r0  = s * 8;
    const int j0  = 2 * c;
    const int bid = 1 + s;

    // ---- one-time init ----
    for (int idx = tid; idx < G_DIM * H_DIM; idx += THREADS) {
        int gg = idx / H_DIM, k = idx % H_DIM;
        Ws[k * G_DIM + gg] = W_hh[idx];
    }
    for (int idx = tid; idx < G_DIM * I_DIM; idx += THREADS) {
        int gg = idx / I_DIM, i = idx % I_DIM;
        Ws[(H_DIM + i) * G_DIM + gg] = W_ih[idx];
    }
    for (int idx = tid; idx < HD_FLOATS; idx += THREADS) HD[idx] = 0.0f;

    GateB gb;
    gb.bR0  = b_ih[j0]      + b_hh[j0];
    gb.bR1  = b_ih[j0 + 1]  + b_hh[j0 + 1];
    gb.bZ0  = b_ih[64 + j0] + b_hh[64 + j0];
    gb.bZ1  = b_ih[65 + j0] + b_hh[65 + j0];
    gb.bIN0 = b_ih[128 + j0]; gb.bIN1 = b_ih[129 + j0];
    gb.bHN0 = b_hh[128 + j0]; gb.bHN1 = b_hh[129 + j0];

    // geometry
    const int rr  = 2 * (r0 + 4 * pr);           // A row float offset (4 rows)
    const int hw0 = j0 * S_DUP;
    const int hw1 = (j0 + 1) * S_DUP;

    // q-even stager role: lane c stages row r0+4*pr+(c>>3), cols (c&7)*4..+4
    const int srow  = r0 + 4 * pr + (c >> 3);
    const int scol4 = (c & 7) * 4;
    const int xdw   = scol4 * S_DUP + 2 * srow;
    const float* xptr = seq + (size_t)(bb + srow) * T * I_DIM + scol4;

    float2 hh0 = make_float2(0.f, 0.f), hh1 = hh0;

    // ---- prologue: q-even warps stage x(0) -> XD[0] ----
    if (!kodd) {
        float4 v0 = *reinterpret_cast<const float4*>(xptr);
        #pragma unroll
        for (int i = 0; i < 4; ++i) {
            float vv = (&v0.x)[i];
            *reinterpret_cast<float2*>(&XD[xdw + i * S_DUP]) = make_float2(vv, vv);
        }
    }
    __syncthreads();

    // ---- main loop ----
    for (int t = 0; t < T; ++t) {
        const int par = t & 1;

        if (!kodd) {
            // ======== q-even: prefetch x(t+1); GEMM h-k[0,48); ship l2,3 ====
            float4 pf;
            const bool ld = (t + 1 < T);
            if (ld) pf = *reinterpret_cast<const float4*>(xptr + (size_t)(t + 1) * I_DIM);

            u64 R[4] = {0, 0, 0, 0}, Z[4] = {0, 0, 0, 0}, N[4] = {0, 0, 0, 0};
            {
                const float* hb = HD + rr;
                const float* wb = Ws + j0;
                #pragma unroll 8
                for (int k = 0; k < 48; ++k) {
                    KG4(hb, wb, R, Z, N)
                    hb += S_DUP; wb += G_DIM;
                }
            }
            SCb[SCI(pr, 2, 0)] = R[2]; SCb[SCI(pr, 2, 1)] = Z[2]; SCb[SCI(pr, 2, 2)] = N[2];
            SCb[SCI(pr, 3, 0)] = R[3]; SCb[SCI(pr, 3, 1)] = Z[3]; SCb[SCI(pr, 3, 2)] = N[3];
            barx(bid);

            // ======== phase 2: stage x(t+1) -> XD[par^1]; epilogue l0,1 =====
            if (ld) {
                float* dst = XD + (par ^ 1) * XD_FLOATS + xdw;
                #pragma unroll
                for (int i = 0; i < 4; ++i) {
                    float vv = (&pf.x)[i];
                    *reinterpret_cast<float2*>(dst + i * S_DUP) = make_float2(vv, vv);
                }
            }
            {
                u64 sR = add2(R[0], SCb[SCI(pr, 0, 0)]);
                u64 sZ = add2(Z[0], SCb[SCI(pr, 0, 1)]);
                u64 sN = add2(N[0], SCb[SCI(pr, 0, 2)]);
                u64 sX = SCb[SCI(pr, 0, 3)];
                gate_row(sR, sZ, sN, sX, gb, hh0);
                const int gr2 = 2 * (r0 + 4 * pr + 0);
                *reinterpret_cast<float2*>(&HD[hw0 + gr2]) = make_float2(hh0.x, hh0.x);
                *reinterpret_cast<float2*>(&HD[hw1 + gr2]) = make_float2(hh0.y, hh0.y);
            }
            {
                u64 sR = add2(R[1], SCb[SCI(pr, 1, 0)]);
                u64 sZ = add2(Z[1], SCb[SCI(pr, 1, 1)]);
                u64 sN = add2(N[1], SCb[SCI(pr, 1, 2)]);
                u64 sX = SCb[SCI(pr, 1, 3)];
                gate_row(sR, sZ, sN, sX, gb, hh1);
                const int gr2 = 2 * (r0 + 4 * pr + 1);
                *reinterpret_cast<float2*>(&HD[hw0 + gr2]) = make_float2(hh1.x, hh1.x);
                *reinterpret_cast<float2*>(&HD[hw1 + gr2]) = make_float2(hh1.y, hh1.y);
            }
            barx(bid);
        } else {
            // ======== q-odd: GEMM h-k[48,64) + x-k[0,32); ship l0,1 =========
            u64 R[4]  = {0, 0, 0, 0}, Z[4]  = {0, 0, 0, 0};
            u64 Nh[4] = {0, 0, 0, 0}, Nx[4] = {0, 0, 0, 0};
            {
                const float* hb = HD + 48 * S_DUP + rr;
                const float* wb = Ws + 48 * G_DIM + j0;
                #pragma unroll 8
                for (int k = 0; k < 16; ++k) {
                    KG4(hb, wb, R, Z, Nh)
                    hb += S_DUP; wb += G_DIM;
                }
            }
            {
                const float* xb = XD + par * XD_FLOATS + rr;
                const float* wb = Ws + H_DIM * G_DIM + j0;
                #pragma unroll 8
                for (int k = 0; k < I_DIM; ++k) {
                    KG4(xb, wb, R, Z, Nx)
                    xb += S_DUP; wb += G_DIM;
                }
            }
            SCb[SCI(pr, 0, 0)] = R[0]; SCb[SCI(pr, 0, 1)] = Z[0];
            SCb[SCI(pr, 0, 2)] = Nh[0]; SCb[SCI(pr, 0, 3)] = Nx[0];
            SCb[SCI(pr, 1, 0)] = R[1]; SCb[SCI(pr, 1, 1)] = Z[1];
            SCb[SCI(pr, 1, 2)] = Nh[1]; SCb[SCI(pr, 1, 3)] = Nx[1];
            barx(bid);

            // ======== phase 2: epilogue l2,3 ================================
            {
                u64 sR = add2(SCb[SCI(pr, 2, 0)], R[2]);
                u64 sZ = add2(SCb[SCI(pr, 2, 1)], Z[2]);
                u64 sN = add2(SCb[SCI(pr, 2, 2)], Nh[2]);
                u64 sX = Nx[2];
                gate_row(sR, sZ, sN, sX, gb, hh0);
                const int gr2 = 2 * (r0 + 4 * pr + 2);
                *reinterpret_cast<float2*>(&HD[hw0 + gr2]) = make_float2(hh0.x, hh0.x);
                *reinterpret_cast<float2*>(&HD[hw1 + gr2]) = make_float2(hh0.y, hh0.y);
            }
            {
                u64 sR = add2(SCb[SCI(pr, 3, 0)], R[3]);
                u64 sZ = add2(SCb[SCI(pr, 3, 1)], Z[3]);
                u64 sN = add2(SCb[SCI(pr, 3, 2)], Nh[3]);
                u64 sX = Nx[3];
                gate_row(sR, sZ, sN, sX, gb, hh1);
                const int gr2 = 2 * (r0 + 4 * pr + 3);
                *reinterpret_cast<float2*>(&HD[hw0 + gr2]) = make_float2(hh1.x, hh1.x);
                *reinterpret_cast<float2*>(&HD[hw1 + gr2]) = make_float2(hh1.y, hh1.y);
            }
            barx(bid);
        }
    }

    // ---- final output: each warp owns 2 rows ----
    const int lbase = kodd ? 2 : 0;
    const int g0 = bb + r0 + 4 * pr + lbase;
    *reinterpret_cast<float2*>(&out[(size_t)(g0 + 0) * H_DIM + j0]) = hh0;
    *reinterpret_cast<float2*>(&out[(size_t)(g0 + 1) * H_DIM + j0]) = hh1;
}

extern "C" void kernel_launch(void* const* d_in, const int* in_sizes, int n_in,
                              void* d_out, int out_size) {
    const float* seq  = (const float*)d_in[0];
    const float* W_ih = (const float*)d_in[1];
    const float* W_hh = (const float*)d_in[2];
    const float* b_ih = (const float*)d_in[3];
    const float* b_hh = (const float*)d_in[4];
    float* out = (float*)d_out;

    const int B = out_size / H_DIM;
    const int T = in_sizes[0] / (B * I_DIM);

    cudaFuncSetAttribute(gru_fwd_kernel,
                         cudaFuncAttributeMaxDynamicSharedMemorySize, SMEM_BYTES);

    const int grid = (B + ROWS_PER_CTA - 1) / ROWS_PER_CTA;
    gru_fwd_kernel<<<grid, THREADS, SMEM_BYTES>>>(seq, W_ih, W_hh, b_ih, b_hh,
                                                  out, B, T);
}